// round 7
// baseline (speedup 1.0000x reference)
#include <cuda_runtime.h>
#include <cstdint>

#define B_ 8
#define V_ 8192
#define N_ 2048
#define C_ 128
#define GRID_ 128
#define THR_ 512

typedef unsigned long long ull;

// ---------- f32x2 helpers (sm_100+ packed fp32: SASS FFMA2) ----------
__device__ __forceinline__ ull pk2(float lo, float hi) {
    ull r; asm("mov.b64 %0, {%1, %2};" : "=l"(r) : "f"(lo), "f"(hi)); return r;
}
__device__ __forceinline__ void upk2(ull v, float& lo, float& hi) {
    asm("mov.b64 {%0, %1}, %2;" : "=f"(lo), "=f"(hi) : "l"(v));
}
__device__ __forceinline__ ull ffma2(ull a, ull b, ull c) {
    ull d; asm("fma.rn.f32x2 %0, %1, %2, %3;" : "=l"(d) : "l"(a), "l"(b), "l"(c)); return d;
}

// ---------- device scratch ----------
__device__ float g_buf[B_ * N_];
__device__ unsigned int bar1, bar_done;

// =====================================================================
// ONE persistent kernel, grid=128 (1 CTA/SM), 512 threads, 96KB dyn smem.
//
// Phase 1 (R5 layout): g table. Block: 128 rows (2x64 subtiles).
//   Warp = 4 rows (uniform X broadcast), lane = 4 outputs. 4x4 FFMA2 tile.
// Grid barrier.
// Phase 2: argmin+gather, block=(b:8|vc:16) -> 512 verts, full N in smem.
//   Thread = 8 verts x 256-pt slice (slice-major: warp shares slice ->
//   point loads warp-uniform). Vertex xyz splatted to f32x2 regs once;
//   2 uniform LDS.128 per point-pair serve 8 verts (24 FFMA2).
//   Best-2 segments per (vert,slice) -> smem (transposed, conflict-free)
//   -> per-vertex lex combine -> exact 2-segment rescan -> gather g_buf.
// =====================================================================
__global__ void __launch_bounds__(THR_, 1)
kernelFused(const float* __restrict__ verts,
            const float* __restrict__ gpos,
            const float* __restrict__ processed,
            const float* __restrict__ W1,
            const float* __restrict__ b1,
            const float* __restrict__ W2,
            const float* __restrict__ b2,
            float* __restrict__ out) {
    extern __shared__ char sm[];
    // phase1 overlay
    ull*   Ws = (ull*)sm;                     // 64KB packed W1
    float* Xs = (float*)(sm + 65536);         // 32KB X tile
    // phase2 overlay
    float* pts  = (float*)sm;                 // 32KB pair-packed points
    float* cval = (float*)(sm + 32768);       // 16 x 512 floats = 32KB
    int*   cseg = (int*)(sm + 65536);         // 16 x 512 ints   = 32KB
    __shared__ float red[64][33];

    const int t   = threadIdx.x;
    const int bid = blockIdx.x;

    // ---------------- Phase 1: g table (R5 layout) ----------------
#pragma unroll
    for (int k = 0; k < 16; k++) {
        int i = t + k * THR_;                 // 0..8191
        int c2 = i >> 7, d = i & 127;
        Ws[i] = pk2(W1[(2 * c2) * C_ + d], W1[(2 * c2 + 1) * C_ + d]);
    }

    const int tr = t >> 5;        // warp 0..15 -> 4 rows each
    const int td = t & 31;        // lane       -> 4 outputs each
    const int r0 = tr * 4;
    const int d0 = td * 4;
    const ulonglong2* Wsv = (const ulonglong2*)Ws;

#pragma unroll 1
    for (int h = 0; h < 2; h++) {
        const int rb = bid * 128 + h * 64;

        const float4* src = (const float4*)(processed + (size_t)rb * C_);
        float4* dst = (float4*)Xs;
#pragma unroll
        for (int k = 0; k < 4; k++) dst[t + k * THR_] = src[t + k * THR_];
        __syncthreads();

        ull acc[4][4];
#pragma unroll
        for (int i = 0; i < 4; i++)
#pragma unroll
            for (int j = 0; j < 4; j++) acc[i][j] = 0ull;

#pragma unroll 8
        for (int c2 = 0; c2 < 64; c2++) {
            ull x2[4];
#pragma unroll
            for (int i = 0; i < 4; i++)
                x2[i] = *(const ull*)&Xs[(r0 + i) * 128 + 2 * c2];  // warp-bcast
            ull w2[4];
            {
                ulonglong2 wa = Wsv[c2 * 64 + td * 2];
                ulonglong2 wb = Wsv[c2 * 64 + td * 2 + 1];
                w2[0] = wa.x; w2[1] = wa.y; w2[2] = wb.x; w2[3] = wb.y;
            }
#pragma unroll
            for (int i = 0; i < 4; i++)
#pragma unroll
                for (int j = 0; j < 4; j++)
                    acc[i][j] = ffma2(x2[i], w2[j], acc[i][j]);
        }

        float part[4] = {0.f, 0.f, 0.f, 0.f};
#pragma unroll
        for (int j = 0; j < 4; j++) {
            float b1j = b1[d0 + j];
            float w2j = W2[d0 + j];
#pragma unroll
            for (int i = 0; i < 4; i++) {
                float lo, hi; upk2(acc[i][j], lo, hi);
                float hv = fmaxf(lo + hi + b1j, 0.f);
                part[i] = fmaf(hv, w2j, part[i]);
            }
        }
#pragma unroll
        for (int i = 0; i < 4; i++) red[r0 + i][td] = part[i];
        __syncthreads();

        if (t < 64) {
            float s = b2[0];
#pragma unroll
            for (int k = 0; k < 32; k++) s += red[t][k];
            g_buf[rb + t] = s;
        }
        __syncthreads();
    }

    // ---------------- Grid barrier ----------------
    __threadfence();
    __syncthreads();
    if (t == 0) {
        atomicAdd(&bar1, 1u);
        while (*(volatile unsigned int*)&bar1 < GRID_) __nanosleep(64);
    }
    __syncthreads();
    __threadfence();

    // ---------------- Phase 2: argmin + gather ----------------
    const int vc = bid & 15;
    const int b  = bid >> 4;
    const int v0 = vc * 512;

    // Pair-packed full-N tile: pair j -> {x0,x1,y0,y1}{z0,z1,pp0,pp1}
#pragma unroll 1
    for (int j = t; j < N_ / 2; j += THR_) {
        const float* p0 = gpos + ((size_t)b * N_ + 2 * j) * 3;
        float x0 = p0[0], y0 = p0[1], z0 = p0[2];
        float x1 = p0[3], y1 = p0[4], z1 = p0[5];
        float pp0 = __fmaf_rn(z0, z0, __fmaf_rn(y0, y0, __fmul_rn(x0, x0)));
        float pp1 = __fmaf_rn(z1, z1, __fmaf_rn(y1, y1, __fmul_rn(x1, x1)));
        float4* d = (float4*)&pts[j * 8];
        d[0] = make_float4(x0, x1, y0, y1);
        d[1] = make_float4(z0, z1, pp0, pp1);
    }
    __syncthreads();

    // Thread: slice ns (256 points), 8 verts (vg + q*64)
    const int ns = t >> 6;      // 0..7 (constant within a warp)
    const int vg = t & 63;

    ull VX[8], VY[8], VZ[8];    // splatted -2*v
#pragma unroll
    for (int q = 0; q < 8; q++) {
        const float* vp = verts + ((size_t)b * V_ + v0 + vg + q * 64) * 3;
        float x = -2.f * vp[0], y = -2.f * vp[1], z = -2.f * vp[2];
        VX[q] = pk2(x, x); VY[q] = pk2(y, y); VZ[q] = pk2(z, z);
    }

    const float INF = __int_as_float(0x7f800000);
    float best[8], sec[8];
    int sgpk[8];                // bits0-7 sgA, bits8-15 sgB (local 0..7)
#pragma unroll
    for (int q = 0; q < 8; q++) { best[q] = INF; sec[q] = INF; sgpk[q] = 0; }

    // 8 segments of 32 points (16 pairs) within this slice
#pragma unroll 1
    for (int s = 0; s < 8; s++) {
        float m[8];
#pragma unroll
        for (int q = 0; q < 8; q++) m[q] = INF;
        const ulonglong2* base = (const ulonglong2*)&pts[(ns * 128 + s * 16) * 8];
#pragma unroll 4
        for (int k = 0; k < 16; k++) {
            ulonglong2 a  = base[2 * k];       // {x0,x1},{y0,y1}
            ulonglong2 bq = base[2 * k + 1];   // {z0,z1},{pp0,pp1}
#pragma unroll
            for (int q = 0; q < 8; q++) {
                ull sc = ffma2(VZ[q], bq.x,
                          ffma2(VY[q], a.y,
                           ffma2(VX[q], a.x, bq.y)));
                float lo, hi; upk2(sc, lo, hi);
                m[q] = fminf(m[q], fminf(lo, hi));
            }
        }
#pragma unroll
        for (int q = 0; q < 8; q++) {
            int sp = sgpk[q];
            if (m[q] < best[q]) {
                sec[q] = best[q]; sgpk[q] = ((sp & 0xff) << 8) | s;
                best[q] = m[q];
            } else if (m[q] < sec[q]) {
                sec[q] = m[q]; sgpk[q] = (sp & 0xff) | (s << 8);
            }
        }
    }

    // Write partials, transposed: cval[entry][vloc], entry = ns*2 + {0,1}
#pragma unroll
    for (int q = 0; q < 8; q++) {
        int vloc = vg + q * 64;
        int gA = ns * 8 + (sgpk[q] & 0xff);
        int gB = ns * 8 + (sgpk[q] >> 8);
        cval[(ns * 2 + 0) * 512 + vloc] = best[q];
        cseg[(ns * 2 + 0) * 512 + vloc] = gA;
        cval[(ns * 2 + 1) * 512 + vloc] = sec[q];
        cseg[(ns * 2 + 1) * 512 + vloc] = gB;
    }
    __syncthreads();

    // Combine: thread t owns vertex v0+t. Lex (val, seg) best-2 of 16.
    {
        float bv = INF, sv = INF;
        int bs = 64, ss = 64;
#pragma unroll
        for (int e = 0; e < 16; e++) {
            float val = cval[e * 512 + t];     // lanes contiguous: no conflict
            int   sg  = cseg[e * 512 + t];
            bool better = (val < bv) || (val == bv && sg < bs);
            if (better) {
                sv = bv; ss = bs; bv = val; bs = sg;
            } else if ((val < sv) || (val == sv && sg < ss)) {
                sv = val; ss = sg;
            }
        }

        // Exact rescan (reference rounding) of the two segments, ascending.
        const float* vp = verts + ((size_t)b * V_ + v0 + t) * 3;
        float vx = vp[0], vy = vp[1], vz = vp[2];
        float nvx = -2.f * vx, nvy = -2.f * vy, nvz = -2.f * vz;
        float vv = __fmaf_rn(vz, vz, __fmaf_rn(vy, vy, __fmul_rn(vx, vx)));

        int lo = min(bs, ss);
        int hi = max(bs, ss);
        float cur = INF;
        int idx = 0;
#pragma unroll 1
        for (int pass = 0; pass < 2; pass++) {
            if (pass == 1 && hi == lo) break;
            int sb = (pass == 0 ? lo : hi) * 32;
#pragma unroll 1
            for (int i = 0; i < 32; i++) {
                int p = sb + i;
                const float* qp = &pts[(p >> 1) * 8 + (p & 1)];
                float s2 = __fmaf_rn(nvz, qp[4],
                            __fmaf_rn(nvy, qp[2],
                             __fmul_rn(nvx, qp[0])));
                float d2 = __fadd_rn(__fadd_rn(vv, s2), qp[6]);
                if (d2 < cur) { cur = d2; idx = p; }
            }
        }
        out[b * V_ + v0 + t] = g_buf[b * N_ + idx];
    }

    // ---------------- Exit: reset barrier (last block) ----------------
    __syncthreads();
    if (t == 0) {
        unsigned int r = atomicAdd(&bar_done, 1u);
        if (r == GRID_ - 1) {
            atomicExch(&bar1, 0u);
            atomicExch(&bar_done, 0u);
        }
    }
}

// =====================================================================
extern "C" void kernel_launch(void* const* d_in, const int* in_sizes, int n_in,
                              void* d_out, int out_size) {
    const float* verts = (const float*)d_in[0];   // [8,8192,3]
    const float* gpos  = (const float*)d_in[1];   // [8,2048,3]
    const float* proc  = (const float*)d_in[2];   // [8,2048,128]
    const float* W1    = (const float*)d_in[3];   // [128,128]
    const float* b1    = (const float*)d_in[4];   // [128]
    const float* W2    = (const float*)d_in[5];   // [128,1]
    const float* b2    = (const float*)d_in[6];   // [1]
    float* out = (float*)d_out;                   // [8,8192,1]

    cudaFuncSetAttribute(kernelFused, cudaFuncAttributeMaxDynamicSharedMemorySize,
                         96 * 1024);
    kernelFused<<<GRID_, THR_, 96 * 1024>>>(verts, gpos, proc, W1, b1, W2, b2, out);
}

// round 8
// speedup vs baseline: 1.6035x; 1.6035x over previous
#include <cuda_runtime.h>
#include <cstdint>

#define B_ 8
#define V_ 8192
#define N_ 2048
#define C_ 128
#define GRID_ 128
#define THR_ 512

typedef unsigned long long ull;

// ---------- f32x2 helpers (sm_100+ packed fp32: SASS FFMA2) ----------
__device__ __forceinline__ ull pk2(float lo, float hi) {
    ull r; asm("mov.b64 %0, {%1, %2};" : "=l"(r) : "f"(lo), "f"(hi)); return r;
}
__device__ __forceinline__ void upk2(ull v, float& lo, float& hi) {
    asm("mov.b64 {%0, %1}, %2;" : "=f"(lo), "=f"(hi) : "l"(v));
}
__device__ __forceinline__ ull ffma2(ull a, ull b, ull c) {
    ull d; asm("fma.rn.f32x2 %0, %1, %2, %3;" : "=l"(d) : "l"(a), "l"(b), "l"(c)); return d;
}

// ---------- device scratch ----------
__device__ float g_buf[B_ * N_];
__device__ unsigned int bar1, bar_done;

// =====================================================================
// ONE persistent kernel, grid=128 (1 CTA/SM), 512 threads, 96KB dyn smem.
//
// Phase 1: g table (R5 layout: warp=4 rows uniform-bcast X, lane=4 outs).
// Grid barrier.
// Phase 2: argmin+gather, block=(b:8|vc:16) -> 512 verts, full N in smem.
//   Thread = Q=4 verts x 512-pt slice (slice-major: warp shares slice ->
//   point LDS warp-uniform; 512 LDS.128/thread, 4x fewer than R5;
//   splats = 24 regs, 8x fewer than R7 -> NO SPILLS).
//   Best-2 segs per (vert,slice) -> smem transposed -> lex combine ->
//   exact 2-segment rescan (1 thread/vertex) -> gather g_buf.
// =====================================================================
__global__ void __launch_bounds__(THR_, 1)
kernelFused(const float* __restrict__ verts,
            const float* __restrict__ gpos,
            const float* __restrict__ processed,
            const float* __restrict__ W1,
            const float* __restrict__ b1,
            const float* __restrict__ W2,
            const float* __restrict__ b2,
            float* __restrict__ out) {
    extern __shared__ char sm[];
    // phase1 overlay
    ull*   Ws = (ull*)sm;                     // 64KB packed W1
    float* Xs = (float*)(sm + 65536);         // 32KB X tile
    // phase2 overlay
    float* pts  = (float*)sm;                 // 32KB pair-packed points
    float* cval = (float*)(sm + 32768);       // 8 x 512 floats = 16KB
    int*   cseg = (int*)(sm + 49152);         // 8 x 512 ints   = 16KB
    __shared__ float red[64][33];

    const int t   = threadIdx.x;
    const int bid = blockIdx.x;

    // ---------------- Phase 1: g table ----------------
#pragma unroll
    for (int k = 0; k < 16; k++) {
        int i = t + k * THR_;                 // 0..8191
        int c2 = i >> 7, d = i & 127;
        Ws[i] = pk2(W1[(2 * c2) * C_ + d], W1[(2 * c2 + 1) * C_ + d]);
    }

    const int tr = t >> 5;        // warp 0..15 -> 4 rows each
    const int td = t & 31;        // lane       -> 4 outputs each
    const int r0 = tr * 4;
    const int d0 = td * 4;
    const ulonglong2* Wsv = (const ulonglong2*)Ws;

#pragma unroll 1
    for (int h = 0; h < 2; h++) {
        const int rb = bid * 128 + h * 64;

        const float4* src = (const float4*)(processed + (size_t)rb * C_);
        float4* dst = (float4*)Xs;
#pragma unroll
        for (int k = 0; k < 4; k++) dst[t + k * THR_] = src[t + k * THR_];
        __syncthreads();

        ull acc[4][4];
#pragma unroll
        for (int i = 0; i < 4; i++)
#pragma unroll
            for (int j = 0; j < 4; j++) acc[i][j] = 0ull;

#pragma unroll 8
        for (int c2 = 0; c2 < 64; c2++) {
            ull x2[4];
#pragma unroll
            for (int i = 0; i < 4; i++)
                x2[i] = *(const ull*)&Xs[(r0 + i) * 128 + 2 * c2];  // warp-bcast
            ull w2[4];
            {
                ulonglong2 wa = Wsv[c2 * 64 + td * 2];
                ulonglong2 wb = Wsv[c2 * 64 + td * 2 + 1];
                w2[0] = wa.x; w2[1] = wa.y; w2[2] = wb.x; w2[3] = wb.y;
            }
#pragma unroll
            for (int i = 0; i < 4; i++)
#pragma unroll
                for (int j = 0; j < 4; j++)
                    acc[i][j] = ffma2(x2[i], w2[j], acc[i][j]);
        }

        float part[4] = {0.f, 0.f, 0.f, 0.f};
#pragma unroll
        for (int j = 0; j < 4; j++) {
            float b1j = b1[d0 + j];
            float w2j = W2[d0 + j];
#pragma unroll
            for (int i = 0; i < 4; i++) {
                float lo, hi; upk2(acc[i][j], lo, hi);
                float hv = fmaxf(lo + hi + b1j, 0.f);
                part[i] = fmaf(hv, w2j, part[i]);
            }
        }
#pragma unroll
        for (int i = 0; i < 4; i++) red[r0 + i][td] = part[i];
        __syncthreads();

        if (t < 64) {
            float s = b2[0];
#pragma unroll
            for (int k = 0; k < 32; k++) s += red[t][k];
            g_buf[rb + t] = s;
        }
        __syncthreads();
    }

    // ---------------- Grid barrier ----------------
    __threadfence();
    __syncthreads();
    if (t == 0) {
        atomicAdd(&bar1, 1u);
        while (*(volatile unsigned int*)&bar1 < GRID_) __nanosleep(64);
    }
    __syncthreads();
    __threadfence();

    // ---------------- Phase 2: argmin + gather ----------------
    const int vc = bid & 15;
    const int b  = bid >> 4;
    const int v0 = vc * 512;

    // Pair-packed full-N tile: pair j -> {x0,x1,y0,y1}{z0,z1,pp0,pp1}
#pragma unroll 1
    for (int j = t; j < N_ / 2; j += THR_) {
        const float* p0 = gpos + ((size_t)b * N_ + 2 * j) * 3;
        float x0 = p0[0], y0 = p0[1], z0 = p0[2];
        float x1 = p0[3], y1 = p0[4], z1 = p0[5];
        float pp0 = __fmaf_rn(z0, z0, __fmaf_rn(y0, y0, __fmul_rn(x0, x0)));
        float pp1 = __fmaf_rn(z1, z1, __fmaf_rn(y1, y1, __fmul_rn(x1, x1)));
        float4* d = (float4*)&pts[j * 8];
        d[0] = make_float4(x0, x1, y0, y1);
        d[1] = make_float4(z0, z1, pp0, pp1);
    }
    __syncthreads();

    // Thread: slice ns (512 points), 4 verts (vg + q*128)
    const int ns = t >> 7;      // 0..3 (constant within a warp)
    const int vg = t & 127;

    ull VX[4], VY[4], VZ[4];    // splatted -2*v : 24 regs
#pragma unroll
    for (int q = 0; q < 4; q++) {
        const float* vp = verts + ((size_t)b * V_ + v0 + vg + q * 128) * 3;
        float x = -2.f * vp[0], y = -2.f * vp[1], z = -2.f * vp[2];
        VX[q] = pk2(x, x); VY[q] = pk2(y, y); VZ[q] = pk2(z, z);
    }

    const float INF = __int_as_float(0x7f800000);
    float best[4], sec[4];
    int sgpk[4];                // bits0-7 sgA, bits8-15 sgB (local 0..15)
#pragma unroll
    for (int q = 0; q < 4; q++) { best[q] = INF; sec[q] = INF; sgpk[q] = 0; }

    // 16 segments of 32 points (16 pairs) within this slice
#pragma unroll 1
    for (int s = 0; s < 16; s++) {
        float m0 = INF, m1 = INF, m2 = INF, m3 = INF;
        const ulonglong2* base = (const ulonglong2*)&pts[(ns * 256 + s * 16) * 8];
#pragma unroll 4
        for (int k = 0; k < 16; k++) {
            ulonglong2 a  = base[2 * k];       // {x0,x1},{y0,y1}
            ulonglong2 bq = base[2 * k + 1];   // {z0,z1},{pp0,pp1}
            {
                ull sc = ffma2(VZ[0], bq.x, ffma2(VY[0], a.y, ffma2(VX[0], a.x, bq.y)));
                float lo, hi; upk2(sc, lo, hi);
                m0 = fminf(m0, fminf(lo, hi));
            }
            {
                ull sc = ffma2(VZ[1], bq.x, ffma2(VY[1], a.y, ffma2(VX[1], a.x, bq.y)));
                float lo, hi; upk2(sc, lo, hi);
                m1 = fminf(m1, fminf(lo, hi));
            }
            {
                ull sc = ffma2(VZ[2], bq.x, ffma2(VY[2], a.y, ffma2(VX[2], a.x, bq.y)));
                float lo, hi; upk2(sc, lo, hi);
                m2 = fminf(m2, fminf(lo, hi));
            }
            {
                ull sc = ffma2(VZ[3], bq.x, ffma2(VY[3], a.y, ffma2(VX[3], a.x, bq.y)));
                float lo, hi; upk2(sc, lo, hi);
                m3 = fminf(m3, fminf(lo, hi));
            }
        }
        float m[4] = {m0, m1, m2, m3};
#pragma unroll
        for (int q = 0; q < 4; q++) {
            int sp = sgpk[q];
            if (m[q] < best[q]) {
                sec[q] = best[q]; sgpk[q] = ((sp & 0xff) << 8) | s;
                best[q] = m[q];
            } else if (m[q] < sec[q]) {
                sec[q] = m[q]; sgpk[q] = (sp & 0xff) | (s << 8);
            }
        }
    }

    // Write partials, transposed: entry e = ns*2 + {0,1}, vloc = vg + q*128
#pragma unroll
    for (int q = 0; q < 4; q++) {
        int vloc = vg + q * 128;
        int gA = ns * 16 + (sgpk[q] & 0xff);
        int gB = ns * 16 + (sgpk[q] >> 8);
        cval[(ns * 2 + 0) * 512 + vloc] = best[q];
        cseg[(ns * 2 + 0) * 512 + vloc] = gA;
        cval[(ns * 2 + 1) * 512 + vloc] = sec[q];
        cseg[(ns * 2 + 1) * 512 + vloc] = gB;
    }
    __syncthreads();

    // Combine: thread t owns vertex v0+t. Lex (val, seg) best-2 of 8.
    {
        float bv = INF, sv = INF;
        int bs = 64, ss = 64;
#pragma unroll
        for (int e = 0; e < 8; e++) {
            float val = cval[e * 512 + t];     // lanes contiguous: no conflict
            int   sg  = cseg[e * 512 + t];
            bool better = (val < bv) || (val == bv && sg < bs);
            if (better) {
                sv = bv; ss = bs; bv = val; bs = sg;
            } else if ((val < sv) || (val == sv && sg < ss)) {
                sv = val; ss = sg;
            }
        }

        // Exact rescan (reference rounding) of the two segments, ascending.
        const float* vp = verts + ((size_t)b * V_ + v0 + t) * 3;
        float vx = vp[0], vy = vp[1], vz = vp[2];
        float nvx = -2.f * vx, nvy = -2.f * vy, nvz = -2.f * vz;
        float vv = __fmaf_rn(vz, vz, __fmaf_rn(vy, vy, __fmul_rn(vx, vx)));

        int lo = min(bs, ss);
        int hi = max(bs, ss);
        float cur = INF;
        int idx = 0;
#pragma unroll 1
        for (int pass = 0; pass < 2; pass++) {
            if (pass == 1 && hi == lo) break;
            int sb = (pass == 0 ? lo : hi) * 32;
#pragma unroll 1
            for (int i = 0; i < 32; i++) {
                int p = sb + i;
                const float* qp = &pts[(p >> 1) * 8 + (p & 1)];
                float s2 = __fmaf_rn(nvz, qp[4],
                            __fmaf_rn(nvy, qp[2],
                             __fmul_rn(nvx, qp[0])));
                float d2 = __fadd_rn(__fadd_rn(vv, s2), qp[6]);
                if (d2 < cur) { cur = d2; idx = p; }
            }
        }
        out[b * V_ + v0 + t] = g_buf[b * N_ + idx];
    }

    // ---------------- Exit: reset barrier (last block) ----------------
    __syncthreads();
    if (t == 0) {
        unsigned int r = atomicAdd(&bar_done, 1u);
        if (r == GRID_ - 1) {
            atomicExch(&bar1, 0u);
            atomicExch(&bar_done, 0u);
        }
    }
}

// =====================================================================
extern "C" void kernel_launch(void* const* d_in, const int* in_sizes, int n_in,
                              void* d_out, int out_size) {
    const float* verts = (const float*)d_in[0];   // [8,8192,3]
    const float* gpos  = (const float*)d_in[1];   // [8,2048,3]
    const float* proc  = (const float*)d_in[2];   // [8,2048,128]
    const float* W1    = (const float*)d_in[3];   // [128,128]
    const float* b1    = (const float*)d_in[4];   // [128]
    const float* W2    = (const float*)d_in[5];   // [128,1]
    const float* b2    = (const float*)d_in[6];   // [1]
    float* out = (float*)d_out;                   // [8,8192,1]

    cudaFuncSetAttribute(kernelFused, cudaFuncAttributeMaxDynamicSharedMemorySize,
                         96 * 1024);
    kernelFused<<<GRID_, THR_, 96 * 1024>>>(verts, gpos, proc, W1, b1, W2, b2, out);
}

// round 9
// speedup vs baseline: 1.7351x; 1.0821x over previous
#include <cuda_runtime.h>
#include <cstdint>

#define B_ 8
#define V_ 8192
#define N_ 2048
#define C_ 128
#define GRID_ 128
#define THR_ 512

typedef unsigned long long ull;

// ---------- f32x2 helpers (sm_100+ packed fp32: SASS FFMA2) ----------
__device__ __forceinline__ ull pk2(float lo, float hi) {
    ull r; asm("mov.b64 %0, {%1, %2};" : "=l"(r) : "f"(lo), "f"(hi)); return r;
}
__device__ __forceinline__ void upk2(ull v, float& lo, float& hi) {
    asm("mov.b64 {%0, %1}, %2;" : "=f"(lo), "=f"(hi) : "l"(v));
}
__device__ __forceinline__ ull ffma2(ull a, ull b, ull c) {
    ull d; asm("fma.rn.f32x2 %0, %1, %2, %3;" : "=l"(d) : "l"(a), "l"(b), "l"(c)); return d;
}

// ---------- device scratch ----------
__device__ float g_buf[B_ * N_];
__device__ unsigned int bar1, bar_done;

// =====================================================================
// ONE persistent kernel, grid=128 (1 CTA/SM), 512 threads, 96KB dyn smem.
//
// Phase 1: g table. NEW W smem layout (split halves, 16B lane stride ->
//   4 wf per LDS.128 instead of 8) + pairwise-fused X LDS.128 loads
//   (warp-uniform). Same accumulation order -> g bit-identical to R8.
// Grid barrier.
// Phase 2: UNCHANGED from R8 (Q=4 verts x 512-pt slice, best-2 segs,
//   exact reference-rounding rescan, smem combine, gather).
// =====================================================================
__global__ void __launch_bounds__(THR_, 1)
kernelFused(const float* __restrict__ verts,
            const float* __restrict__ gpos,
            const float* __restrict__ processed,
            const float* __restrict__ W1,
            const float* __restrict__ b1,
            const float* __restrict__ W2,
            const float* __restrict__ b2,
            float* __restrict__ out) {
    extern __shared__ char sm[];
    // phase1 overlay
    ull*   Ws = (ull*)sm;                     // 64KB packed W1 (split-half layout)
    float* Xs = (float*)(sm + 65536);         // 32KB X tile
    // phase2 overlay
    float* pts  = (float*)sm;                 // 32KB pair-packed points
    float* cval = (float*)(sm + 32768);       // 8 x 512 floats = 16KB
    int*   cseg = (int*)(sm + 49152);         // 8 x 512 ints   = 16KB
    __shared__ float red[64][33];

    const int t   = threadIdx.x;
    const int bid = blockIdx.x;

    // ---------------- Phase 1: g table ----------------
    // Split-half layout: for r in [0,64):  Ws[c2*128 + r]      -> d = 4*(r>>1) + (r&1)
    //                    for r in [64,128): Ws[c2*128 + r]     -> d = 4*((r-64)>>1) + (r&1) + 2
    // Thread td then reads d = {4td,4td+1} at ull idx c2*128 + 2td (16B lane stride)
    //                  and d = {4td+2,4td+3} at c2*128 + 64 + 2td.
#pragma unroll
    for (int k = 0; k < 16; k++) {
        int i = t + k * THR_;                 // 0..8191
        int c2 = i >> 7;
        int r = i & 127;
        int d = 4 * ((r & 63) >> 1) + (r & 1) + ((r >> 6) << 1);
        Ws[i] = pk2(W1[(2 * c2) * C_ + d], W1[(2 * c2 + 1) * C_ + d]);
    }

    const int tr = t >> 5;        // warp 0..15 -> 4 rows each
    const int td = t & 31;        // lane       -> 4 outputs each
    const int r0 = tr * 4;
    const int d0 = td * 4;
    const ulonglong2* Wsv2 = (const ulonglong2*)Ws;

#pragma unroll 1
    for (int h = 0; h < 2; h++) {
        const int rb = bid * 128 + h * 64;

        const float4* src = (const float4*)(processed + (size_t)rb * C_);
        float4* dst = (float4*)Xs;
#pragma unroll
        for (int k = 0; k < 4; k++) dst[t + k * THR_] = src[t + k * THR_];
        __syncthreads();

        ull acc[4][4];
#pragma unroll
        for (int i = 0; i < 4; i++)
#pragma unroll
            for (int j = 0; j < 4; j++) acc[i][j] = 0ull;

#pragma unroll 4
        for (int c4 = 0; c4 < 32; c4++) {     // two c2 per step
            // X: one warp-uniform LDS.128 per row covers c2 = 2c4, 2c4+1
            ulonglong2 xv[4];
#pragma unroll
            for (int i = 0; i < 4; i++)
                xv[i] = *(const ulonglong2*)&Xs[(r0 + i) * 128 + 4 * c4];
#pragma unroll
            for (int half = 0; half < 2; half++) {
                const int c2 = 2 * c4 + half;
                // W: two LDS.128 at 16B lane stride (4 wf each)
                ulonglong2 wa = Wsv2[c2 * 64 + td];        // d = 4td, 4td+1
                ulonglong2 wb = Wsv2[c2 * 64 + 32 + td];   // d = 4td+2, 4td+3
                ull w2[4] = {wa.x, wa.y, wb.x, wb.y};
#pragma unroll
                for (int i = 0; i < 4; i++) {
                    ull xi = half ? xv[i].y : xv[i].x;
#pragma unroll
                    for (int j = 0; j < 4; j++)
                        acc[i][j] = ffma2(xi, w2[j], acc[i][j]);
                }
            }
        }

        float part[4] = {0.f, 0.f, 0.f, 0.f};
#pragma unroll
        for (int j = 0; j < 4; j++) {
            float b1j = b1[d0 + j];
            float w2j = W2[d0 + j];
#pragma unroll
            for (int i = 0; i < 4; i++) {
                float lo, hi; upk2(acc[i][j], lo, hi);
                float hv = fmaxf(lo + hi + b1j, 0.f);
                part[i] = fmaf(hv, w2j, part[i]);
            }
        }
#pragma unroll
        for (int i = 0; i < 4; i++) red[r0 + i][td] = part[i];
        __syncthreads();

        if (t < 64) {
            float s = b2[0];
#pragma unroll
            for (int k = 0; k < 32; k++) s += red[t][k];
            g_buf[rb + t] = s;
        }
        __syncthreads();
    }

    // ---------------- Grid barrier ----------------
    __threadfence();
    __syncthreads();
    if (t == 0) {
        atomicAdd(&bar1, 1u);
        while (*(volatile unsigned int*)&bar1 < GRID_) __nanosleep(64);
    }
    __syncthreads();
    __threadfence();

    // ---------------- Phase 2: argmin + gather (R8, unchanged) ----------------
    const int vc = bid & 15;
    const int b  = bid >> 4;
    const int v0 = vc * 512;

    // Pair-packed full-N tile: pair j -> {x0,x1,y0,y1}{z0,z1,pp0,pp1}
#pragma unroll 1
    for (int j = t; j < N_ / 2; j += THR_) {
        const float* p0 = gpos + ((size_t)b * N_ + 2 * j) * 3;
        float x0 = p0[0], y0 = p0[1], z0 = p0[2];
        float x1 = p0[3], y1 = p0[4], z1 = p0[5];
        float pp0 = __fmaf_rn(z0, z0, __fmaf_rn(y0, y0, __fmul_rn(x0, x0)));
        float pp1 = __fmaf_rn(z1, z1, __fmaf_rn(y1, y1, __fmul_rn(x1, x1)));
        float4* d = (float4*)&pts[j * 8];
        d[0] = make_float4(x0, x1, y0, y1);
        d[1] = make_float4(z0, z1, pp0, pp1);
    }
    __syncthreads();

    // Thread: slice ns (512 points), 4 verts (vg + q*128)
    const int ns = t >> 7;      // 0..3 (constant within a warp)
    const int vg = t & 127;

    ull VX[4], VY[4], VZ[4];    // splatted -2*v : 24 regs
#pragma unroll
    for (int q = 0; q < 4; q++) {
        const float* vp = verts + ((size_t)b * V_ + v0 + vg + q * 128) * 3;
        float x = -2.f * vp[0], y = -2.f * vp[1], z = -2.f * vp[2];
        VX[q] = pk2(x, x); VY[q] = pk2(y, y); VZ[q] = pk2(z, z);
    }

    const float INF = __int_as_float(0x7f800000);
    float best[4], sec[4];
    int sgpk[4];                // bits0-7 sgA, bits8-15 sgB (local 0..15)
#pragma unroll
    for (int q = 0; q < 4; q++) { best[q] = INF; sec[q] = INF; sgpk[q] = 0; }

    // 16 segments of 32 points (16 pairs) within this slice
#pragma unroll 1
    for (int s = 0; s < 16; s++) {
        float m0 = INF, m1 = INF, m2 = INF, m3 = INF;
        const ulonglong2* base = (const ulonglong2*)&pts[(ns * 256 + s * 16) * 8];
#pragma unroll 4
        for (int k = 0; k < 16; k++) {
            ulonglong2 a  = base[2 * k];       // {x0,x1},{y0,y1}
            ulonglong2 bq = base[2 * k + 1];   // {z0,z1},{pp0,pp1}
            {
                ull sc = ffma2(VZ[0], bq.x, ffma2(VY[0], a.y, ffma2(VX[0], a.x, bq.y)));
                float lo, hi; upk2(sc, lo, hi);
                m0 = fminf(m0, fminf(lo, hi));
            }
            {
                ull sc = ffma2(VZ[1], bq.x, ffma2(VY[1], a.y, ffma2(VX[1], a.x, bq.y)));
                float lo, hi; upk2(sc, lo, hi);
                m1 = fminf(m1, fminf(lo, hi));
            }
            {
                ull sc = ffma2(VZ[2], bq.x, ffma2(VY[2], a.y, ffma2(VX[2], a.x, bq.y)));
                float lo, hi; upk2(sc, lo, hi);
                m2 = fminf(m2, fminf(lo, hi));
            }
            {
                ull sc = ffma2(VZ[3], bq.x, ffma2(VY[3], a.y, ffma2(VX[3], a.x, bq.y)));
                float lo, hi; upk2(sc, lo, hi);
                m3 = fminf(m3, fminf(lo, hi));
            }
        }
        float m[4] = {m0, m1, m2, m3};
#pragma unroll
        for (int q = 0; q < 4; q++) {
            int sp = sgpk[q];
            if (m[q] < best[q]) {
                sec[q] = best[q]; sgpk[q] = ((sp & 0xff) << 8) | s;
                best[q] = m[q];
            } else if (m[q] < sec[q]) {
                sec[q] = m[q]; sgpk[q] = (sp & 0xff) | (s << 8);
            }
        }
    }

    // Write partials, transposed: entry e = ns*2 + {0,1}, vloc = vg + q*128
#pragma unroll
    for (int q = 0; q < 4; q++) {
        int vloc = vg + q * 128;
        int gA = ns * 16 + (sgpk[q] & 0xff);
        int gB = ns * 16 + (sgpk[q] >> 8);
        cval[(ns * 2 + 0) * 512 + vloc] = best[q];
        cseg[(ns * 2 + 0) * 512 + vloc] = gA;
        cval[(ns * 2 + 1) * 512 + vloc] = sec[q];
        cseg[(ns * 2 + 1) * 512 + vloc] = gB;
    }
    __syncthreads();

    // Combine: thread t owns vertex v0+t. Lex (val, seg) best-2 of 8.
    {
        float bv = INF, sv = INF;
        int bs = 64, ss = 64;
#pragma unroll
        for (int e = 0; e < 8; e++) {
            float val = cval[e * 512 + t];     // lanes contiguous: no conflict
            int   sg  = cseg[e * 512 + t];
            bool better = (val < bv) || (val == bv && sg < bs);
            if (better) {
                sv = bv; ss = bs; bv = val; bs = sg;
            } else if ((val < sv) || (val == sv && sg < ss)) {
                sv = val; ss = sg;
            }
        }

        // Exact rescan (reference rounding) of the two segments, ascending.
        const float* vp = verts + ((size_t)b * V_ + v0 + t) * 3;
        float vx = vp[0], vy = vp[1], vz = vp[2];
        float nvx = -2.f * vx, nvy = -2.f * vy, nvz = -2.f * vz;
        float vv = __fmaf_rn(vz, vz, __fmaf_rn(vy, vy, __fmul_rn(vx, vx)));

        int lo = min(bs, ss);
        int hi = max(bs, ss);
        float cur = INF;
        int idx = 0;
#pragma unroll 1
        for (int pass = 0; pass < 2; pass++) {
            if (pass == 1 && hi == lo) break;
            int sb = (pass == 0 ? lo : hi) * 32;
#pragma unroll 1
            for (int i = 0; i < 32; i++) {
                int p = sb + i;
                const float* qp = &pts[(p >> 1) * 8 + (p & 1)];
                float s2 = __fmaf_rn(nvz, qp[4],
                            __fmaf_rn(nvy, qp[2],
                             __fmul_rn(nvx, qp[0])));
                float d2 = __fadd_rn(__fadd_rn(vv, s2), qp[6]);
                if (d2 < cur) { cur = d2; idx = p; }
            }
        }
        out[b * V_ + v0 + t] = g_buf[b * N_ + idx];
    }

    // ---------------- Exit: reset barrier (last block) ----------------
    __syncthreads();
    if (t == 0) {
        unsigned int r = atomicAdd(&bar_done, 1u);
        if (r == GRID_ - 1) {
            atomicExch(&bar1, 0u);
            atomicExch(&bar_done, 0u);
        }
    }
}

// =====================================================================
extern "C" void kernel_launch(void* const* d_in, const int* in_sizes, int n_in,
                              void* d_out, int out_size) {
    const float* verts = (const float*)d_in[0];   // [8,8192,3]
    const float* gpos  = (const float*)d_in[1];   // [8,2048,3]
    const float* proc  = (const float*)d_in[2];   // [8,2048,128]
    const float* W1    = (const float*)d_in[3];   // [128,128]
    const float* b1    = (const float*)d_in[4];   // [128]
    const float* W2    = (const float*)d_in[5];   // [128,1]
    const float* b2    = (const float*)d_in[6];   // [1]
    float* out = (float*)d_out;                   // [8,8192,1]

    cudaFuncSetAttribute(kernelFused, cudaFuncAttributeMaxDynamicSharedMemorySize,
                         96 * 1024);
    kernelFused<<<GRID_, THR_, 96 * 1024>>>(verts, gpos, proc, W1, b1, W2, b2, out);
}

// round 11
// speedup vs baseline: 2.5338x; 1.4603x over previous
#include <cuda_runtime.h>
#include <cstdint>

#define B_ 8
#define V_ 8192
#define N_ 2048
#define C_ 128
#define GRID_ 128
#define THR_ 512

typedef unsigned long long ull;

// ---------- f32x2 helpers (sm_100+ packed fp32) ----------
__device__ __forceinline__ ull pk2(float lo, float hi) {
    ull r; asm("mov.b64 %0, {%1, %2};" : "=l"(r) : "f"(lo), "f"(hi)); return r;
}
__device__ __forceinline__ void upk2(ull v, float& lo, float& hi) {
    asm("mov.b64 {%0, %1}, %2;" : "=f"(lo), "=f"(hi) : "l"(v));
}
__device__ __forceinline__ ull ffma2(ull a, ull b, ull c) {
    ull d; asm("fma.rn.f32x2 %0, %1, %2, %3;" : "=l"(d) : "l"(a), "l"(b), "l"(c)); return d;
}

// ---------- device scratch ----------
__device__ float g_buf[B_ * N_];
__device__ unsigned int bar1, bar_done;

// =====================================================================
// ONE persistent kernel, grid=128 (1 CTA/SM), 512 threads, 96KB dyn smem.
//
// Phase 1: g table (split-half W layout, fused X LDS.128).
//   -> t0 ARRIVES on grid barrier (release) but nobody waits yet.
// Phase 2: screening (needs only verts/gpos): Q=4 verts x 512-pt slice,
//   scalar fminf running mins (min.f32x2 doesn't exist in PTX),
//   best-2 segments -> smem -> lex combine ->
//   exact reference-rounding rescan with wide LDS.128 loads.
//   -> THEN wait on the grid barrier (fully hidden by screening)
//   -> gather out = g_buf[argmin].
// =====================================================================
__global__ void __launch_bounds__(THR_, 1)
kernelFused(const float* __restrict__ verts,
            const float* __restrict__ gpos,
            const float* __restrict__ processed,
            const float* __restrict__ W1,
            const float* __restrict__ b1,
            const float* __restrict__ W2,
            const float* __restrict__ b2,
            float* __restrict__ out) {
    extern __shared__ char sm[];
    // phase1 overlay
    ull*   Ws = (ull*)sm;                     // 64KB packed W1 (split-half layout)
    float* Xs = (float*)(sm + 65536);         // 32KB X tile
    // phase2 overlay
    float* pts  = (float*)sm;                 // 32KB pair-packed points
    float* cval = (float*)(sm + 32768);       // 8 x 512 floats = 16KB
    int*   cseg = (int*)(sm + 49152);         // 8 x 512 ints   = 16KB
    __shared__ float red[64][33];

    const int t   = threadIdx.x;
    const int bid = blockIdx.x;

    // ---------------- Phase 1: g table ----------------
#pragma unroll
    for (int k = 0; k < 16; k++) {
        int i = t + k * THR_;                 // 0..8191
        int c2 = i >> 7;
        int r = i & 127;
        int d = 4 * ((r & 63) >> 1) + (r & 1) + ((r >> 6) << 1);
        Ws[i] = pk2(W1[(2 * c2) * C_ + d], W1[(2 * c2 + 1) * C_ + d]);
    }

    const int tr = t >> 5;        // warp 0..15 -> 4 rows each
    const int td = t & 31;        // lane       -> 4 outputs each
    const int r0 = tr * 4;
    const int d0 = td * 4;
    const ulonglong2* Wsv2 = (const ulonglong2*)Ws;

#pragma unroll 1
    for (int h = 0; h < 2; h++) {
        const int rb = bid * 128 + h * 64;

        const float4* src = (const float4*)(processed + (size_t)rb * C_);
        float4* dst = (float4*)Xs;
#pragma unroll
        for (int k = 0; k < 4; k++) dst[t + k * THR_] = src[t + k * THR_];
        __syncthreads();

        ull acc[4][4];
#pragma unroll
        for (int i = 0; i < 4; i++)
#pragma unroll
            for (int j = 0; j < 4; j++) acc[i][j] = 0ull;

#pragma unroll 4
        for (int c4 = 0; c4 < 32; c4++) {     // two c2 per step
            ulonglong2 xv[4];
#pragma unroll
            for (int i = 0; i < 4; i++)
                xv[i] = *(const ulonglong2*)&Xs[(r0 + i) * 128 + 4 * c4];
#pragma unroll
            for (int half = 0; half < 2; half++) {
                const int c2 = 2 * c4 + half;
                ulonglong2 wa = Wsv2[c2 * 64 + td];        // d = 4td, 4td+1
                ulonglong2 wb = Wsv2[c2 * 64 + 32 + td];   // d = 4td+2, 4td+3
                ull w2[4] = {wa.x, wa.y, wb.x, wb.y};
#pragma unroll
                for (int i = 0; i < 4; i++) {
                    ull xi = half ? xv[i].y : xv[i].x;
#pragma unroll
                    for (int j = 0; j < 4; j++)
                        acc[i][j] = ffma2(xi, w2[j], acc[i][j]);
                }
            }
        }

        float part[4] = {0.f, 0.f, 0.f, 0.f};
#pragma unroll
        for (int j = 0; j < 4; j++) {
            float b1j = b1[d0 + j];
            float w2j = W2[d0 + j];
#pragma unroll
            for (int i = 0; i < 4; i++) {
                float lo, hi; upk2(acc[i][j], lo, hi);
                float hv = fmaxf(lo + hi + b1j, 0.f);
                part[i] = fmaf(hv, w2j, part[i]);
            }
        }
#pragma unroll
        for (int i = 0; i < 4; i++) red[r0 + i][td] = part[i];
        __syncthreads();

        if (t < 64) {
            float s = b2[0];
#pragma unroll
            for (int k = 0; k < 32; k++) s += red[t][k];
            g_buf[rb + t] = s;
        }
        __syncthreads();
    }

    // ---- Grid barrier ARRIVE only (release g_buf); wait comes later ----
    if (t == 0) {
        __threadfence();
        atomicAdd(&bar1, 1u);
    }

    // ---------------- Phase 2: screening (independent of g_buf) ----------------
    const int vc = bid & 15;
    const int b  = bid >> 4;
    const int v0 = vc * 512;

    // Pair-packed full-N tile: pair j -> {x0,x1,y0,y1}{z0,z1,pp0,pp1}
#pragma unroll 1
    for (int j = t; j < N_ / 2; j += THR_) {
        const float* p0 = gpos + ((size_t)b * N_ + 2 * j) * 3;
        float x0 = p0[0], y0 = p0[1], z0 = p0[2];
        float x1 = p0[3], y1 = p0[4], z1 = p0[5];
        float pp0 = __fmaf_rn(z0, z0, __fmaf_rn(y0, y0, __fmul_rn(x0, x0)));
        float pp1 = __fmaf_rn(z1, z1, __fmaf_rn(y1, y1, __fmul_rn(x1, x1)));
        float4* d = (float4*)&pts[j * 8];
        d[0] = make_float4(x0, x1, y0, y1);
        d[1] = make_float4(z0, z1, pp0, pp1);
    }
    __syncthreads();

    // Thread: slice ns (512 points), 4 verts (vg + q*128)
    const int ns = t >> 7;      // 0..3 (constant within a warp)
    const int vg = t & 127;

    ull VX[4], VY[4], VZ[4];    // splatted -2*v : 24 regs
#pragma unroll
    for (int q = 0; q < 4; q++) {
        const float* vp = verts + ((size_t)b * V_ + v0 + vg + q * 128) * 3;
        float x = -2.f * vp[0], y = -2.f * vp[1], z = -2.f * vp[2];
        VX[q] = pk2(x, x); VY[q] = pk2(y, y); VZ[q] = pk2(z, z);
    }

    const float INF = __int_as_float(0x7f800000);
    float best[4], sec[4];
    int sgpk[4];                // bits0-7 sgA, bits8-15 sgB (local 0..15)
#pragma unroll
    for (int q = 0; q < 4; q++) { best[q] = INF; sec[q] = INF; sgpk[q] = 0; }

    // 16 segments of 32 points (16 pairs) within this slice
#pragma unroll 1
    for (int s = 0; s < 16; s++) {
        float m0 = INF, m1 = INF, m2 = INF, m3 = INF;
        const ulonglong2* base = (const ulonglong2*)&pts[(ns * 256 + s * 16) * 8];
#pragma unroll 4
        for (int k = 0; k < 16; k++) {
            ulonglong2 a  = base[2 * k];       // {x0,x1},{y0,y1}
            ulonglong2 bq = base[2 * k + 1];   // {z0,z1},{pp0,pp1}
            {
                ull sc = ffma2(VZ[0], bq.x, ffma2(VY[0], a.y, ffma2(VX[0], a.x, bq.y)));
                float lo, hi; upk2(sc, lo, hi);
                m0 = fminf(m0, fminf(lo, hi));
            }
            {
                ull sc = ffma2(VZ[1], bq.x, ffma2(VY[1], a.y, ffma2(VX[1], a.x, bq.y)));
                float lo, hi; upk2(sc, lo, hi);
                m1 = fminf(m1, fminf(lo, hi));
            }
            {
                ull sc = ffma2(VZ[2], bq.x, ffma2(VY[2], a.y, ffma2(VX[2], a.x, bq.y)));
                float lo, hi; upk2(sc, lo, hi);
                m2 = fminf(m2, fminf(lo, hi));
            }
            {
                ull sc = ffma2(VZ[3], bq.x, ffma2(VY[3], a.y, ffma2(VX[3], a.x, bq.y)));
                float lo, hi; upk2(sc, lo, hi);
                m3 = fminf(m3, fminf(lo, hi));
            }
        }
        float m[4] = {m0, m1, m2, m3};
#pragma unroll
        for (int q = 0; q < 4; q++) {
            int sp = sgpk[q];
            if (m[q] < best[q]) {
                sec[q] = best[q]; sgpk[q] = ((sp & 0xff) << 8) | s;
                best[q] = m[q];
            } else if (m[q] < sec[q]) {
                sec[q] = m[q]; sgpk[q] = (sp & 0xff) | (s << 8);
            }
        }
    }

    // Write partials, transposed: entry e = ns*2 + {0,1}, vloc = vg + q*128
#pragma unroll
    for (int q = 0; q < 4; q++) {
        int vloc = vg + q * 128;
        int gA = ns * 16 + (sgpk[q] & 0xff);
        int gB = ns * 16 + (sgpk[q] >> 8);
        cval[(ns * 2 + 0) * 512 + vloc] = best[q];
        cseg[(ns * 2 + 0) * 512 + vloc] = gA;
        cval[(ns * 2 + 1) * 512 + vloc] = sec[q];
        cseg[(ns * 2 + 1) * 512 + vloc] = gB;
    }
    __syncthreads();

    // Combine + exact rescan: thread t owns vertex v0+t.
    int idx = 0;
    {
        float bv = INF, sv = INF;
        int bs = 64, ss = 64;
#pragma unroll
        for (int e = 0; e < 8; e++) {
            float val = cval[e * 512 + t];     // lanes contiguous: no conflict
            int   sg  = cseg[e * 512 + t];
            bool better = (val < bv) || (val == bv && sg < bs);
            if (better) {
                sv = bv; ss = bs; bv = val; bs = sg;
            } else if ((val < sv) || (val == sv && sg < ss)) {
                sv = val; ss = sg;
            }
        }

        // Exact rescan (reference rounding) of the two segments, ascending.
        const float* vp = verts + ((size_t)b * V_ + v0 + t) * 3;
        float vx = vp[0], vy = vp[1], vz = vp[2];
        float nvx = -2.f * vx, nvy = -2.f * vy, nvz = -2.f * vz;
        float vv = __fmaf_rn(vz, vz, __fmaf_rn(vy, vy, __fmul_rn(vx, vx)));

        int lo = min(bs, ss);
        int hi = max(bs, ss);
        float cur = INF;
#pragma unroll 1
        for (int pass = 0; pass < 2; pass++) {
            if (pass == 1 && hi == lo) break;
            int sb = (pass == 0 ? lo : hi) * 32;
            const ulonglong2* basep = (const ulonglong2*)&pts[(sb >> 1) * 8];
#pragma unroll 1
            for (int j = 0; j < 16; j++) {
                ulonglong2 A  = basep[2 * j];      // {x0,x1},{y0,y1}
                ulonglong2 Bq = basep[2 * j + 1];  // {z0,z1},{pp0,pp1}
                float x0, x1, y0, y1, z0, z1, w0, w1;
                upk2(A.x, x0, x1); upk2(A.y, y0, y1);
                upk2(Bq.x, z0, z1); upk2(Bq.y, w0, w1);
                // point 2j (exact reference rounding)
                float s2 = __fmaf_rn(nvz, z0, __fmaf_rn(nvy, y0, __fmul_rn(nvx, x0)));
                float d2 = __fadd_rn(__fadd_rn(vv, s2), w0);
                if (d2 < cur) { cur = d2; idx = sb + 2 * j; }
                // point 2j+1
                float s3 = __fmaf_rn(nvz, z1, __fmaf_rn(nvy, y1, __fmul_rn(nvx, x1)));
                float d3 = __fadd_rn(__fadd_rn(vv, s3), w1);
                if (d3 < cur) { cur = d3; idx = sb + 2 * j + 1; }
            }
        }
    }

    // ---- Grid barrier WAIT (hidden behind ~40us of screening) ----
    if (t == 0) {
        while (*(volatile unsigned int*)&bar1 < GRID_) __nanosleep(64);
    }
    __syncthreads();
    __threadfence();

    // ---- Gather ----
    out[b * V_ + v0 + t] = g_buf[b * N_ + idx];

    // ---------------- Exit: reset barrier (last block) ----------------
    __syncthreads();
    if (t == 0) {
        unsigned int r = atomicAdd(&bar_done, 1u);
        if (r == GRID_ - 1) {
            atomicExch(&bar1, 0u);
            atomicExch(&bar_done, 0u);
        }
    }
}

// =====================================================================
extern "C" void kernel_launch(void* const* d_in, const int* in_sizes, int n_in,
                              void* d_out, int out_size) {
    const float* verts = (const float*)d_in[0];   // [8,8192,3]
    const float* gpos  = (const float*)d_in[1];   // [8,2048,3]
    const float* proc  = (const float*)d_in[2];   // [8,2048,128]
    const float* W1    = (const float*)d_in[3];   // [128,128]
    const float* b1    = (const float*)d_in[4];   // [128]
    const float* W2    = (const float*)d_in[5];   // [128,1]
    const float* b2    = (const float*)d_in[6];   // [1]
    float* out = (float*)d_out;                   // [8,8192,1]

    cudaFuncSetAttribute(kernelFused, cudaFuncAttributeMaxDynamicSharedMemorySize,
                         96 * 1024);
    kernelFused<<<GRID_, THR_, 96 * 1024>>>(verts, gpos, proc, W1, b1, W2, b2, out);
}